// round 1
// baseline (speedup 1.0000x reference)
#include <cuda_runtime.h>

#define B_DIM 8
#define T_DIM 2048
#define D_DIM 1024
#define NEG_INF -1.0e9f

// Tiling: 128x128 C-tile, K-step 8, 256 threads, 8x8 microtile per thread.
#define BM 128
#define BN 128
#define BK 8

// ---------------------------------------------------------------------------
// Kernel 1: scores[b,t,s] = sum_d x[b,t,d]*x[b,s,d], masked (keep s<t, else -1e9)
// Upper-triangular tiles (colTile > rowTile) are pure -1e9 fills: no GEMM work.
// ---------------------------------------------------------------------------
__global__ __launch_bounds__(256) void scores_kernel(const float* __restrict__ x,
                                                     float* __restrict__ w) {
    const int b = blockIdx.z;
    const int rowTile = blockIdx.y;
    const int colTile = blockIdx.x;
    const int rowStart = rowTile * BM;
    const int colStart = colTile * BN;
    float* wb = w + (size_t)b * T_DIM * T_DIM;
    const int tid = threadIdx.x;

    if (colTile > rowTile) {
        // fully-masked tile: fill with -1e9 (vectorized)
        const float4 neg = make_float4(NEG_INF, NEG_INF, NEG_INF, NEG_INF);
        for (int i = tid; i < BM * BN / 4; i += 256) {
            int m = i >> 5;           // 32 float4 per 128-col row
            int n4 = (i & 31) << 2;
            *reinterpret_cast<float4*>(
                &wb[(size_t)(rowStart + m) * T_DIM + colStart + n4]) = neg;
        }
        return;
    }

    __shared__ float As[BK][BM];
    __shared__ float Bs[BK][BN];
    const float* xb = x + (size_t)b * T_DIM * D_DIM;

    const int tx = tid & 15;   // 0..15 -> 8 cols each
    const int ty = tid >> 4;   // 0..15 -> 8 rows each
    const int lr = tid >> 1;         // load row 0..127
    const int lk = (tid & 1) << 2;   // load k-quad 0 or 4

    float acc[8][8];
#pragma unroll
    for (int i = 0; i < 8; i++)
#pragma unroll
        for (int j = 0; j < 8; j++) acc[i][j] = 0.0f;

    for (int k0 = 0; k0 < D_DIM; k0 += BK) {
        float4 av = *reinterpret_cast<const float4*>(
            &xb[(size_t)(rowStart + lr) * D_DIM + k0 + lk]);
        float4 bv = *reinterpret_cast<const float4*>(
            &xb[(size_t)(colStart + lr) * D_DIM + k0 + lk]);
        __syncthreads();   // previous iter's compute done before overwrite
        As[lk + 0][lr] = av.x; As[lk + 1][lr] = av.y;
        As[lk + 2][lr] = av.z; As[lk + 3][lr] = av.w;
        Bs[lk + 0][lr] = bv.x; Bs[lk + 1][lr] = bv.y;
        Bs[lk + 2][lr] = bv.z; Bs[lk + 3][lr] = bv.w;
        __syncthreads();

#pragma unroll
        for (int kk = 0; kk < BK; kk++) {
            float a[8], bb[8];
            *reinterpret_cast<float4*>(&a[0]) =
                *reinterpret_cast<const float4*>(&As[kk][ty * 8]);
            *reinterpret_cast<float4*>(&a[4]) =
                *reinterpret_cast<const float4*>(&As[kk][ty * 8 + 4]);
            *reinterpret_cast<float4*>(&bb[0]) =
                *reinterpret_cast<const float4*>(&Bs[kk][tx * 8]);
            *reinterpret_cast<float4*>(&bb[4]) =
                *reinterpret_cast<const float4*>(&Bs[kk][tx * 8 + 4]);
#pragma unroll
            for (int i = 0; i < 8; i++)
#pragma unroll
                for (int j = 0; j < 8; j++)
                    acc[i][j] = fmaf(a[i], bb[j], acc[i][j]);
        }
    }

    const bool needMask = (colTile == rowTile);
#pragma unroll
    for (int i = 0; i < 8; i++) {
        const int t = rowStart + ty * 8 + i;
        float* rowp = &wb[(size_t)t * T_DIM + colStart + tx * 8];
#pragma unroll
        for (int j4 = 0; j4 < 8; j4 += 4) {
            float4 v;
            if (needMask) {
                const int s = colStart + tx * 8 + j4;
                v.x = (s + 0 < t) ? acc[i][j4 + 0] : NEG_INF;
                v.y = (s + 1 < t) ? acc[i][j4 + 1] : NEG_INF;
                v.z = (s + 2 < t) ? acc[i][j4 + 2] : NEG_INF;
                v.w = (s + 3 < t) ? acc[i][j4 + 3] : NEG_INF;
            } else {
                v.x = acc[i][j4 + 0]; v.y = acc[i][j4 + 1];
                v.z = acc[i][j4 + 2]; v.w = acc[i][j4 + 3];
            }
            *reinterpret_cast<float4*>(rowp + j4) = v;
        }
    }
}

// ---------------------------------------------------------------------------
// Kernel 2: in-place row softmax over w (row length T_DIM = 2048)
// One block (256 threads) per row; 8 elements per thread, held in registers.
// ---------------------------------------------------------------------------
__device__ __forceinline__ float warpReduceMax(float m) {
#pragma unroll
    for (int o = 16; o > 0; o >>= 1) m = fmaxf(m, __shfl_xor_sync(0xffffffffu, m, o));
    return m;
}
__device__ __forceinline__ float warpReduceSum(float s) {
#pragma unroll
    for (int o = 16; o > 0; o >>= 1) s += __shfl_xor_sync(0xffffffffu, s, o);
    return s;
}

__global__ __launch_bounds__(256) void softmax_kernel(float* __restrict__ w) {
    float* wr = w + (size_t)blockIdx.x * T_DIM;
    const int tid = threadIdx.x;
    const int lane = tid & 31;
    const int warp = tid >> 5;
    __shared__ float red[8];

    float v[8];
    // two float4 loads: [tid*4 .. tid*4+3] and [1024 + tid*4 ..]
    float4 v0 = *reinterpret_cast<const float4*>(&wr[tid * 4]);
    float4 v1 = *reinterpret_cast<const float4*>(&wr[1024 + tid * 4]);
    v[0] = v0.x; v[1] = v0.y; v[2] = v0.z; v[3] = v0.w;
    v[4] = v1.x; v[5] = v1.y; v[6] = v1.z; v[7] = v1.w;

    float m = v[0];
#pragma unroll
    for (int i = 1; i < 8; i++) m = fmaxf(m, v[i]);
    m = warpReduceMax(m);
    if (lane == 0) red[warp] = m;
    __syncthreads();
    m = red[0];
#pragma unroll
    for (int i = 1; i < 8; i++) m = fmaxf(m, red[i]);
    __syncthreads();   // red reused for sum

    float s = 0.0f;
#pragma unroll
    for (int i = 0; i < 8; i++) {
        v[i] = expf(v[i] - m);
        s += v[i];
    }
    s = warpReduceSum(s);
    if (lane == 0) red[warp] = s;
    __syncthreads();
    s = red[0];
#pragma unroll
    for (int i = 1; i < 8; i++) s += red[i];

    const float inv = 1.0f / s;
    float4 o0 = make_float4(v[0] * inv, v[1] * inv, v[2] * inv, v[3] * inv);
    float4 o1 = make_float4(v[4] * inv, v[5] * inv, v[6] * inv, v[7] * inv);
    *reinterpret_cast<float4*>(&wr[tid * 4]) = o0;
    *reinterpret_cast<float4*>(&wr[1024 + tid * 4]) = o1;
}

// ---------------------------------------------------------------------------
// Kernel 3: att_vec[b,t,d] = sum_s w[b,t,s] * x[b,s,d]
// Causal structure: w[t,s]==0 for s>t (t>=1), so row-tile r only needs
// s-tiles up to its diagonal -> 16*(r+1) K-iterations. Row-tile 0 contains
// row 0 (uniform weights over ALL s) -> full K loop.
// ---------------------------------------------------------------------------
__global__ __launch_bounds__(256) void attvec_kernel(const float* __restrict__ w,
                                                     const float* __restrict__ x,
                                                     float* __restrict__ out) {
    const int b = blockIdx.z;
    const int rowTile = blockIdx.y;   // 16 tiles over t
    const int colTile = blockIdx.x;   // 8 tiles over d
    const int rowStart = rowTile * BM;
    const int colStart = colTile * BN;
    const float* wb = w + (size_t)b * T_DIM * T_DIM;
    const float* xb = x + (size_t)b * T_DIM * D_DIM;
    float* ob = out + (size_t)b * T_DIM * D_DIM;

    __shared__ float As[BK][BM];
    __shared__ float Bs[BK][BN];

    const int tid = threadIdx.x;
    const int tx = tid & 15;
    const int ty = tid >> 4;
    const int lr = tid >> 1;          // A-load row 0..127
    const int lk = (tid & 1) << 2;    // A-load k-quad
    const int bk = tid >> 5;          // B-load k row 0..7
    const int bn4 = (tid & 31) << 2;  // B-load col quad

    float acc[8][8];
#pragma unroll
    for (int i = 0; i < 8; i++)
#pragma unroll
        for (int j = 0; j < 8; j++) acc[i][j] = 0.0f;

    const int numK = (rowTile == 0) ? (T_DIM / BK) : (16 * (rowTile + 1));

    for (int kt = 0; kt < numK; kt++) {
        const int s0 = kt * BK;
        float4 av = *reinterpret_cast<const float4*>(
            &wb[(size_t)(rowStart + lr) * T_DIM + s0 + lk]);
        float4 bv = *reinterpret_cast<const float4*>(
            &xb[(size_t)(s0 + bk) * D_DIM + colStart + bn4]);
        __syncthreads();
        As[lk + 0][lr] = av.x; As[lk + 1][lr] = av.y;
        As[lk + 2][lr] = av.z; As[lk + 3][lr] = av.w;
        *reinterpret_cast<float4*>(&Bs[bk][bn4]) = bv;
        __syncthreads();

#pragma unroll
        for (int kk = 0; kk < BK; kk++) {
            float a[8], bb[8];
            *reinterpret_cast<float4*>(&a[0]) =
                *reinterpret_cast<const float4*>(&As[kk][ty * 8]);
            *reinterpret_cast<float4*>(&a[4]) =
                *reinterpret_cast<const float4*>(&As[kk][ty * 8 + 4]);
            *reinterpret_cast<float4*>(&bb[0]) =
                *reinterpret_cast<const float4*>(&Bs[kk][tx * 8]);
            *reinterpret_cast<float4*>(&bb[4]) =
                *reinterpret_cast<const float4*>(&Bs[kk][tx * 8 + 4]);
#pragma unroll
            for (int i = 0; i < 8; i++)
#pragma unroll
                for (int j = 0; j < 8; j++)
                    acc[i][j] = fmaf(a[i], bb[j], acc[i][j]);
        }
    }

#pragma unroll
    for (int i = 0; i < 8; i++) {
        const int t = rowStart + ty * 8 + i;
        float* rowp = &ob[(size_t)t * D_DIM + colStart + tx * 8];
        *reinterpret_cast<float4*>(rowp + 0) =
            make_float4(acc[i][0], acc[i][1], acc[i][2], acc[i][3]);
        *reinterpret_cast<float4*>(rowp + 4) =
            make_float4(acc[i][4], acc[i][5], acc[i][6], acc[i][7]);
    }
}

// ---------------------------------------------------------------------------
// Launch: d_out = [att_vec (B*T*D) | att_weights (B*T*T)] in tuple order.
// ---------------------------------------------------------------------------
extern "C" void kernel_launch(void* const* d_in, const int* in_sizes, int n_in,
                              void* d_out, int out_size) {
    (void)in_sizes; (void)n_in; (void)out_size;
    const float* x = (const float*)d_in[0];
    float* out = (float*)d_out;
    float* w = out + (size_t)B_DIM * T_DIM * D_DIM;   // weights region

    dim3 g1(T_DIM / BN, T_DIM / BM, B_DIM);
    scores_kernel<<<g1, 256>>>(x, w);

    softmax_kernel<<<B_DIM * T_DIM, 256>>>(w);

    dim3 g3(D_DIM / BN, T_DIM / BM, B_DIM);
    attvec_kernel<<<g3, 256>>>(w, x, out);
}

// round 2
// speedup vs baseline: 2.0828x; 2.0828x over previous
#include <cuda_runtime.h>
#include <cstdint>

#define B_DIM 8
#define T_DIM 2048
#define D_DIM 1024
#define NEG_INF -1.0e9f

#define BM 128
#define BN 128
#define BK 16
#define SST 20   // smem row stride in floats (20*4=80B, 16B-aligned, conflict-free frag reads)

// Scratch: x transposed and split into tf32 hi/lo, layout [b][d][t]
__device__ float g_xT_hi[(size_t)B_DIM * D_DIM * T_DIM];
__device__ float g_xT_lo[(size_t)B_DIM * D_DIM * T_DIM];

__device__ __forceinline__ float to_tf32(float x) {
    uint32_t u;
    asm("cvt.rna.tf32.f32 %0, %1;" : "=r"(u) : "f"(x));
    return __uint_as_float(u);
}

__device__ __forceinline__ void split_store(float* hi, float* lo, float4 v) {
    float hx = to_tf32(v.x), hy = to_tf32(v.y), hz = to_tf32(v.z), hw = to_tf32(v.w);
    *reinterpret_cast<float4*>(hi) = make_float4(hx, hy, hz, hw);
    *reinterpret_cast<float4*>(lo) = make_float4(
        to_tf32(v.x - hx), to_tf32(v.y - hy), to_tf32(v.z - hz), to_tf32(v.w - hw));
}

__device__ __forceinline__ void mma_tf32(float* c, const uint32_t* a, const uint32_t* b) {
    asm volatile(
        "mma.sync.aligned.m16n8k8.row.col.f32.tf32.tf32.f32 "
        "{%0,%1,%2,%3}, {%4,%5,%6,%7}, {%8,%9}, {%0,%1,%2,%3};\n"
        : "+f"(c[0]), "+f"(c[1]), "+f"(c[2]), "+f"(c[3])
        : "r"(a[0]), "r"(a[1]), "r"(a[2]), "r"(a[3]), "r"(b[0]), "r"(b[1]));
}

// ---------------------------------------------------------------------------
// Prep: xT_hi/xT_lo[b][d][t] = tf32 split of x[b][t][d]
// ---------------------------------------------------------------------------
__global__ __launch_bounds__(256) void transpose_split_kernel(const float* __restrict__ x) {
    __shared__ float tile[32][33];
    const int b = blockIdx.z;
    const int t0 = blockIdx.x * 32;
    const int d0 = blockIdx.y * 32;
    const float* xb = x + (size_t)b * T_DIM * D_DIM;
    const int tx = threadIdx.x;  // 0..31
    const int ty = threadIdx.y;  // 0..7
#pragma unroll
    for (int i = 0; i < 32; i += 8)
        tile[ty + i][tx] = xb[(size_t)(t0 + ty + i) * D_DIM + d0 + tx];
    __syncthreads();
    float* oh = g_xT_hi + (size_t)b * D_DIM * T_DIM;
    float* ol = g_xT_lo + (size_t)b * D_DIM * T_DIM;
#pragma unroll
    for (int i = 0; i < 32; i += 8) {
        float v = tile[tx][ty + i];  // = x[t0+tx][d0+ty+i]
        float h = to_tf32(v);
        oh[(size_t)(d0 + ty + i) * T_DIM + t0 + tx] = h;
        ol[(size_t)(d0 + ty + i) * T_DIM + t0 + tx] = to_tf32(v - h);
    }
}

// ---------------------------------------------------------------------------
// Kernel 1: scores = mask(x @ x^T) via tf32-split mma. 128x128 tile per block.
// ---------------------------------------------------------------------------
__global__ __launch_bounds__(256, 2) void scores_kernel(const float* __restrict__ x,
                                                        float* __restrict__ w) {
    const int b = blockIdx.z;
    const int rowTile = blockIdx.y;
    const int colTile = blockIdx.x;
    const int rowStart = rowTile * BM;
    const int colStart = colTile * BN;
    float* wb = w + (size_t)b * T_DIM * T_DIM;
    const int tid = threadIdx.x;

    if (colTile > rowTile) {
        const float4 neg = make_float4(NEG_INF, NEG_INF, NEG_INF, NEG_INF);
        for (int i = tid; i < BM * BN / 4; i += 256) {
            int m = i >> 5;
            int n4 = (i & 31) << 2;
            *reinterpret_cast<float4*>(
                &wb[(size_t)(rowStart + m) * T_DIM + colStart + n4]) = neg;
        }
        return;
    }

    __shared__ float Ah[BM][SST], Al[BM][SST], Bh[BN][SST], Bl[BN][SST];
    const float* xb = x + (size_t)b * T_DIM * D_DIM;

    const int lane = tid & 31, warp = tid >> 5;
    const int wm = (warp & 1) * 64;   // warp m-offset (2 x 64)
    const int wn = (warp >> 1) * 32;  // warp n-offset (4 x 32)
    const int gid = lane >> 2, qid = lane & 3;
    const int lr = tid >> 1;          // loader row 0..127
    const int lk = (tid & 1) * 8;     // loader k-offset 0/8

    float acc[4][4][4];
#pragma unroll
    for (int i = 0; i < 4; i++)
#pragma unroll
        for (int j = 0; j < 4; j++)
#pragma unroll
            for (int q = 0; q < 4; q++) acc[i][j][q] = 0.0f;

    for (int k0 = 0; k0 < D_DIM; k0 += BK) {
        float4 av0 = *reinterpret_cast<const float4*>(&xb[(size_t)(rowStart + lr) * D_DIM + k0 + lk]);
        float4 av1 = *reinterpret_cast<const float4*>(&xb[(size_t)(rowStart + lr) * D_DIM + k0 + lk + 4]);
        float4 bv0 = *reinterpret_cast<const float4*>(&xb[(size_t)(colStart + lr) * D_DIM + k0 + lk]);
        float4 bv1 = *reinterpret_cast<const float4*>(&xb[(size_t)(colStart + lr) * D_DIM + k0 + lk + 4]);
        __syncthreads();
        split_store(&Ah[lr][lk], &Al[lr][lk], av0);
        split_store(&Ah[lr][lk + 4], &Al[lr][lk + 4], av1);
        split_store(&Bh[lr][lk], &Bl[lr][lk], bv0);
        split_store(&Bh[lr][lk + 4], &Bl[lr][lk + 4], bv1);
        __syncthreads();

#pragma unroll
        for (int kb = 0; kb < BK; kb += 8) {
            uint32_t bh[4][2], bl[4][2];
#pragma unroll
            for (int nt = 0; nt < 4; nt++) {
                const int col = wn + nt * 8 + gid;
                bh[nt][0] = __float_as_uint(Bh[col][kb + qid]);
                bh[nt][1] = __float_as_uint(Bh[col][kb + qid + 4]);
                bl[nt][0] = __float_as_uint(Bl[col][kb + qid]);
                bl[nt][1] = __float_as_uint(Bl[col][kb + qid + 4]);
            }
#pragma unroll
            for (int mt = 0; mt < 4; mt++) {
                const int row = wm + mt * 16 + gid;
                uint32_t ah[4], al[4];
                ah[0] = __float_as_uint(Ah[row][kb + qid]);
                ah[1] = __float_as_uint(Ah[row + 8][kb + qid]);
                ah[2] = __float_as_uint(Ah[row][kb + qid + 4]);
                ah[3] = __float_as_uint(Ah[row + 8][kb + qid + 4]);
                al[0] = __float_as_uint(Al[row][kb + qid]);
                al[1] = __float_as_uint(Al[row + 8][kb + qid]);
                al[2] = __float_as_uint(Al[row][kb + qid + 4]);
                al[3] = __float_as_uint(Al[row + 8][kb + qid + 4]);
#pragma unroll
                for (int nt = 0; nt < 4; nt++) {
                    mma_tf32(acc[mt][nt], ah, bh[nt]);
                    mma_tf32(acc[mt][nt], ah, bl[nt]);
                    mma_tf32(acc[mt][nt], al, bh[nt]);
                }
            }
        }
    }

    const bool diag = (colTile == rowTile);
#pragma unroll
    for (int mt = 0; mt < 4; mt++)
#pragma unroll
        for (int nt = 0; nt < 4; nt++) {
            float* c = acc[mt][nt];
            const int t0 = rowStart + wm + mt * 16 + gid;
            const int t1 = t0 + 8;
            const int s0 = colStart + wn + nt * 8 + qid * 2;
            float2 v;
            if (diag) {
                v.x = (s0 < t0) ? c[0] : NEG_INF;
                v.y = (s0 + 1 < t0) ? c[1] : NEG_INF;
            } else {
                v.x = c[0]; v.y = c[1];
            }
            *reinterpret_cast<float2*>(&wb[(size_t)t0 * T_DIM + s0]) = v;
            if (diag) {
                v.x = (s0 < t1) ? c[2] : NEG_INF;
                v.y = (s0 + 1 < t1) ? c[3] : NEG_INF;
            } else {
                v.x = c[2]; v.y = c[3];
            }
            *reinterpret_cast<float2*>(&wb[(size_t)t1 * T_DIM + s0]) = v;
        }
}

// ---------------------------------------------------------------------------
// Kernel 2: row softmax (unchanged from round 1)
// ---------------------------------------------------------------------------
__device__ __forceinline__ float warpReduceMax(float m) {
#pragma unroll
    for (int o = 16; o > 0; o >>= 1) m = fmaxf(m, __shfl_xor_sync(0xffffffffu, m, o));
    return m;
}
__device__ __forceinline__ float warpReduceSum(float s) {
#pragma unroll
    for (int o = 16; o > 0; o >>= 1) s += __shfl_xor_sync(0xffffffffu, s, o);
    return s;
}

__global__ __launch_bounds__(256) void softmax_kernel(float* __restrict__ w) {
    float* wr = w + (size_t)blockIdx.x * T_DIM;
    const int tid = threadIdx.x;
    const int lane = tid & 31;
    const int warp = tid >> 5;
    __shared__ float red[8];

    float v[8];
    float4 v0 = *reinterpret_cast<const float4*>(&wr[tid * 4]);
    float4 v1 = *reinterpret_cast<const float4*>(&wr[1024 + tid * 4]);
    v[0] = v0.x; v[1] = v0.y; v[2] = v0.z; v[3] = v0.w;
    v[4] = v1.x; v[5] = v1.y; v[6] = v1.z; v[7] = v1.w;

    float m = v[0];
#pragma unroll
    for (int i = 1; i < 8; i++) m = fmaxf(m, v[i]);
    m = warpReduceMax(m);
    if (lane == 0) red[warp] = m;
    __syncthreads();
    m = red[0];
#pragma unroll
    for (int i = 1; i < 8; i++) m = fmaxf(m, red[i]);
    __syncthreads();

    float s = 0.0f;
#pragma unroll
    for (int i = 0; i < 8; i++) {
        v[i] = expf(v[i] - m);
        s += v[i];
    }
    s = warpReduceSum(s);
    if (lane == 0) red[warp] = s;
    __syncthreads();
    s = red[0];
#pragma unroll
    for (int i = 1; i < 8; i++) s += red[i];

    const float inv = 1.0f / s;
    *reinterpret_cast<float4*>(&wr[tid * 4]) =
        make_float4(v[0] * inv, v[1] * inv, v[2] * inv, v[3] * inv);
    *reinterpret_cast<float4*>(&wr[1024 + tid * 4]) =
        make_float4(v[4] * inv, v[5] * inv, v[6] * inv, v[7] * inv);
}

// ---------------------------------------------------------------------------
// Kernel 3: att_vec = W @ X via tf32-split mma. A = W (split in-kernel),
// B = precomputed xT hi/lo [d][s] (k = s contiguous). Causal K-loop cut.
// ---------------------------------------------------------------------------
__global__ __launch_bounds__(256, 2) void attvec_kernel(const float* __restrict__ w,
                                                        float* __restrict__ out) {
    const int b = blockIdx.z;
    const int rowTile = blockIdx.y;   // t tiles (16)
    const int colTile = blockIdx.x;   // d tiles (8)
    const int rowStart = rowTile * BM;
    const int colStart = colTile * BN;
    const float* wb = w + (size_t)b * T_DIM * T_DIM;
    const float* xth = g_xT_hi + (size_t)b * D_DIM * T_DIM;
    const float* xtl = g_xT_lo + (size_t)b * D_DIM * T_DIM;
    float* ob = out + (size_t)b * T_DIM * D_DIM;

    __shared__ float Ah[BM][SST], Al[BM][SST], Bh[BN][SST], Bl[BN][SST];

    const int tid = threadIdx.x;
    const int lane = tid & 31, warp = tid >> 5;
    const int wm = (warp & 1) * 64;
    const int wn = (warp >> 1) * 32;
    const int gid = lane >> 2, qid = lane & 3;
    const int lr = tid >> 1;
    const int lk = (tid & 1) * 8;

    float acc[4][4][4];
#pragma unroll
    for (int i = 0; i < 4; i++)
#pragma unroll
        for (int j = 0; j < 4; j++)
#pragma unroll
            for (int q = 0; q < 4; q++) acc[i][j][q] = 0.0f;

    const int numStages = (rowTile == 0) ? (T_DIM / BK) : ((rowTile + 1) * BM / BK);

    for (int st = 0; st < numStages; st++) {
        const int k0 = st * BK;  // s offset
        float4 av0 = *reinterpret_cast<const float4*>(&wb[(size_t)(rowStart + lr) * T_DIM + k0 + lk]);
        float4 av1 = *reinterpret_cast<const float4*>(&wb[(size_t)(rowStart + lr) * T_DIM + k0 + lk + 4]);
        float4 bh0 = *reinterpret_cast<const float4*>(&xth[(size_t)(colStart + lr) * T_DIM + k0 + lk]);
        float4 bh1 = *reinterpret_cast<const float4*>(&xth[(size_t)(colStart + lr) * T_DIM + k0 + lk + 4]);
        float4 bl0 = *reinterpret_cast<const float4*>(&xtl[(size_t)(colStart + lr) * T_DIM + k0 + lk]);
        float4 bl1 = *reinterpret_cast<const float4*>(&xtl[(size_t)(colStart + lr) * T_DIM + k0 + lk + 4]);
        __syncthreads();
        split_store(&Ah[lr][lk], &Al[lr][lk], av0);
        split_store(&Ah[lr][lk + 4], &Al[lr][lk + 4], av1);
        *reinterpret_cast<float4*>(&Bh[lr][lk]) = bh0;
        *reinterpret_cast<float4*>(&Bh[lr][lk + 4]) = bh1;
        *reinterpret_cast<float4*>(&Bl[lr][lk]) = bl0;
        *reinterpret_cast<float4*>(&Bl[lr][lk + 4]) = bl1;
        __syncthreads();

#pragma unroll
        for (int kb = 0; kb < BK; kb += 8) {
            uint32_t bh[4][2], bl[4][2];
#pragma unroll
            for (int nt = 0; nt < 4; nt++) {
                const int col = wn + nt * 8 + gid;
                bh[nt][0] = __float_as_uint(Bh[col][kb + qid]);
                bh[nt][1] = __float_as_uint(Bh[col][kb + qid + 4]);
                bl[nt][0] = __float_as_uint(Bl[col][kb + qid]);
                bl[nt][1] = __float_as_uint(Bl[col][kb + qid + 4]);
            }
#pragma unroll
            for (int mt = 0; mt < 4; mt++) {
                const int row = wm + mt * 16 + gid;
                uint32_t ah[4], al[4];
                ah[0] = __float_as_uint(Ah[row][kb + qid]);
                ah[1] = __float_as_uint(Ah[row + 8][kb + qid]);
                ah[2] = __float_as_uint(Ah[row][kb + qid + 4]);
                ah[3] = __float_as_uint(Ah[row + 8][kb + qid + 4]);
                al[0] = __float_as_uint(Al[row][kb + qid]);
                al[1] = __float_as_uint(Al[row + 8][kb + qid]);
                al[2] = __float_as_uint(Al[row][kb + qid + 4]);
                al[3] = __float_as_uint(Al[row + 8][kb + qid + 4]);
#pragma unroll
                for (int nt = 0; nt < 4; nt++) {
                    mma_tf32(acc[mt][nt], ah, bh[nt]);
                    mma_tf32(acc[mt][nt], ah, bl[nt]);
                    mma_tf32(acc[mt][nt], al, bh[nt]);
                }
            }
        }
    }

#pragma unroll
    for (int mt = 0; mt < 4; mt++)
#pragma unroll
        for (int nt = 0; nt < 4; nt++) {
            float* c = acc[mt][nt];
            const int t0 = rowStart + wm + mt * 16 + gid;
            const int d0 = colStart + wn + nt * 8 + qid * 2;
            *reinterpret_cast<float2*>(&ob[(size_t)t0 * D_DIM + d0]) =
                make_float2(c[0], c[1]);
            *reinterpret_cast<float2*>(&ob[(size_t)(t0 + 8) * D_DIM + d0]) =
                make_float2(c[2], c[3]);
        }
}

// ---------------------------------------------------------------------------
// Launch: d_out = [att_vec (B*T*D) | att_weights (B*T*T)]
// ---------------------------------------------------------------------------
extern "C" void kernel_launch(void* const* d_in, const int* in_sizes, int n_in,
                              void* d_out, int out_size) {
    (void)in_sizes; (void)n_in; (void)out_size;
    const float* x = (const float*)d_in[0];
    float* out = (float*)d_out;
    float* w = out + (size_t)B_DIM * T_DIM * D_DIM;

    dim3 gt(T_DIM / 32, D_DIM / 32, B_DIM);
    transpose_split_kernel<<<gt, dim3(32, 8)>>>(x);

    dim3 g1(T_DIM / BN, T_DIM / BM, B_DIM);
    scores_kernel<<<g1, 256>>>(x, w);

    softmax_kernel<<<B_DIM * T_DIM, 256>>>(w);

    dim3 g3(D_DIM / BN, T_DIM / BM, B_DIM);
    attvec_kernel<<<g3, 256>>>(w, out);
}

// round 3
// speedup vs baseline: 3.4701x; 1.6661x over previous
#include <cuda_runtime.h>
#include <cuda_fp16.h>
#include <cstdint>

#define B_DIM 8
#define T_DIM 2048
#define D_DIM 1024
#define NEG_INF -1.0e9f

#define BM 128
#define BN 128
#define BK 16
#define SSTH 40   // smem row stride in halves (80B: 16B-aligned, frag LDS conflict-free)

// fp16 hi/lo split of x, row-major [b][t][d] and transposed [b][d][t]
__device__ __half g_xh [(size_t)B_DIM * T_DIM * D_DIM];
__device__ __half g_xl [(size_t)B_DIM * T_DIM * D_DIM];
__device__ __half g_xTh[(size_t)B_DIM * D_DIM * T_DIM];
__device__ __half g_xTl[(size_t)B_DIM * D_DIM * T_DIM];

__device__ __forceinline__ void mma_f16(float* c, const uint32_t* a, const uint32_t* b) {
    asm volatile(
        "mma.sync.aligned.m16n8k16.row.col.f32.f16.f16.f32 "
        "{%0,%1,%2,%3}, {%4,%5,%6,%7}, {%8,%9}, {%0,%1,%2,%3};\n"
        : "+f"(c[0]), "+f"(c[1]), "+f"(c[2]), "+f"(c[3])
        : "r"(a[0]), "r"(a[1]), "r"(a[2]), "r"(a[3]), "r"(b[0]), "r"(b[1]));
}

__device__ __forceinline__ void split_f16(float v, __half& h, __half& l) {
    h = __float2half_rn(v);
    l = __float2half_rn(v - __half2float(h));
}

// ---------------------------------------------------------------------------
// Prep: fp16 split of x into [t][d] and [d][t] layouts.
// ---------------------------------------------------------------------------
__global__ __launch_bounds__(256) void prep_kernel(const float* __restrict__ x) {
    __shared__ float tile[32][33];
    const int b = blockIdx.z;
    const int t0 = blockIdx.x * 32;
    const int d0 = blockIdx.y * 32;
    const float* xb = x + (size_t)b * T_DIM * D_DIM;
    const int tx = threadIdx.x;  // 0..31
    const int ty = threadIdx.y;  // 0..7
    const size_t base = (size_t)b * T_DIM * D_DIM;
#pragma unroll
    for (int i = 0; i < 32; i += 8) {
        float v = xb[(size_t)(t0 + ty + i) * D_DIM + d0 + tx];
        tile[ty + i][tx] = v;
        __half h, l;
        split_f16(v, h, l);
        g_xh[base + (size_t)(t0 + ty + i) * D_DIM + d0 + tx] = h;
        g_xl[base + (size_t)(t0 + ty + i) * D_DIM + d0 + tx] = l;
    }
    __syncthreads();
#pragma unroll
    for (int i = 0; i < 32; i += 8) {
        float v = tile[tx][ty + i];  // = x[t0+tx][d0+ty+i]
        __half h, l;
        split_f16(v, h, l);
        g_xTh[base + (size_t)(d0 + ty + i) * T_DIM + t0 + tx] = h;
        g_xTl[base + (size_t)(d0 + ty + i) * T_DIM + t0 + tx] = l;
    }
}

// ---------------------------------------------------------------------------
// Kernel 1: scores = mask(x @ x^T) via fp16-split 3-pass mma (m16n8k16).
// ---------------------------------------------------------------------------
__global__ __launch_bounds__(256, 2) void scores_kernel(float* __restrict__ w) {
    const int b = blockIdx.z;
    const int rowTile = blockIdx.y;
    const int colTile = blockIdx.x;
    const int rowStart = rowTile * BM;
    const int colStart = colTile * BN;
    float* wb = w + (size_t)b * T_DIM * T_DIM;
    const int tid = threadIdx.x;

    if (colTile > rowTile) {
        const float4 neg = make_float4(NEG_INF, NEG_INF, NEG_INF, NEG_INF);
        for (int i = tid; i < BM * BN / 4; i += 256) {
            int m = i >> 5;
            int n4 = (i & 31) << 2;
            *reinterpret_cast<float4*>(
                &wb[(size_t)(rowStart + m) * T_DIM + colStart + n4]) = neg;
        }
        return;
    }

    __shared__ __half Ah[BM][SSTH], Al[BM][SSTH], Bh[BN][SSTH], Bl[BN][SSTH];
    const __half* xhb = g_xh + (size_t)b * T_DIM * D_DIM;
    const __half* xlb = g_xl + (size_t)b * T_DIM * D_DIM;

    const int lane = tid & 31, warp = tid >> 5;
    const int wm = (warp & 1) * 64;
    const int wn = (warp >> 1) * 32;
    const int gid = lane >> 2, qid = lane & 3;
    const int lr = tid >> 1;          // loader row 0..127
    const int lk = (tid & 1) * 8;     // loader k-offset 0/8 (halves)

    float acc[4][4][4];
#pragma unroll
    for (int i = 0; i < 4; i++)
#pragma unroll
        for (int j = 0; j < 4; j++)
#pragma unroll
            for (int q = 0; q < 4; q++) acc[i][j][q] = 0.0f;

    for (int k0 = 0; k0 < D_DIM; k0 += BK) {
        uint4 avh = *reinterpret_cast<const uint4*>(&xhb[(size_t)(rowStart + lr) * D_DIM + k0 + lk]);
        uint4 avl = *reinterpret_cast<const uint4*>(&xlb[(size_t)(rowStart + lr) * D_DIM + k0 + lk]);
        uint4 bvh = *reinterpret_cast<const uint4*>(&xhb[(size_t)(colStart + lr) * D_DIM + k0 + lk]);
        uint4 bvl = *reinterpret_cast<const uint4*>(&xlb[(size_t)(colStart + lr) * D_DIM + k0 + lk]);
        __syncthreads();
        *reinterpret_cast<uint4*>(&Ah[lr][lk]) = avh;
        *reinterpret_cast<uint4*>(&Al[lr][lk]) = avl;
        *reinterpret_cast<uint4*>(&Bh[lr][lk]) = bvh;
        *reinterpret_cast<uint4*>(&Bl[lr][lk]) = bvl;
        __syncthreads();

        uint32_t bhf[4][2], blf[4][2];
#pragma unroll
        for (int nt = 0; nt < 4; nt++) {
            const int col = wn + nt * 8 + gid;
            bhf[nt][0] = *reinterpret_cast<const uint32_t*>(&Bh[col][qid * 2]);
            bhf[nt][1] = *reinterpret_cast<const uint32_t*>(&Bh[col][qid * 2 + 8]);
            blf[nt][0] = *reinterpret_cast<const uint32_t*>(&Bl[col][qid * 2]);
            blf[nt][1] = *reinterpret_cast<const uint32_t*>(&Bl[col][qid * 2 + 8]);
        }
#pragma unroll
        for (int mt = 0; mt < 4; mt++) {
            const int row = wm + mt * 16 + gid;
            uint32_t ah[4], al[4];
            ah[0] = *reinterpret_cast<const uint32_t*>(&Ah[row][qid * 2]);
            ah[1] = *reinterpret_cast<const uint32_t*>(&Ah[row + 8][qid * 2]);
            ah[2] = *reinterpret_cast<const uint32_t*>(&Ah[row][qid * 2 + 8]);
            ah[3] = *reinterpret_cast<const uint32_t*>(&Ah[row + 8][qid * 2 + 8]);
            al[0] = *reinterpret_cast<const uint32_t*>(&Al[row][qid * 2]);
            al[1] = *reinterpret_cast<const uint32_t*>(&Al[row + 8][qid * 2]);
            al[2] = *reinterpret_cast<const uint32_t*>(&Al[row][qid * 2 + 8]);
            al[3] = *reinterpret_cast<const uint32_t*>(&Al[row + 8][qid * 2 + 8]);
#pragma unroll
            for (int nt = 0; nt < 4; nt++) {
                mma_f16(acc[mt][nt], ah, bhf[nt]);
                mma_f16(acc[mt][nt], ah, blf[nt]);
                mma_f16(acc[mt][nt], al, bhf[nt]);
            }
        }
    }

    const bool diag = (colTile == rowTile);
#pragma unroll
    for (int mt = 0; mt < 4; mt++)
#pragma unroll
        for (int nt = 0; nt < 4; nt++) {
            float* c = acc[mt][nt];
            const int t0 = rowStart + wm + mt * 16 + gid;
            const int t1 = t0 + 8;
            const int s0 = colStart + wn + nt * 8 + qid * 2;
            float2 v;
            if (diag) {
                v.x = (s0 < t0) ? c[0] : NEG_INF;
                v.y = (s0 + 1 < t0) ? c[1] : NEG_INF;
            } else {
                v.x = c[0]; v.y = c[1];
            }
            *reinterpret_cast<float2*>(&wb[(size_t)t0 * T_DIM + s0]) = v;
            if (diag) {
                v.x = (s0 < t1) ? c[2] : NEG_INF;
                v.y = (s0 + 1 < t1) ? c[3] : NEG_INF;
            } else {
                v.x = c[2]; v.y = c[3];
            }
            *reinterpret_cast<float2*>(&wb[(size_t)t1 * T_DIM + s0]) = v;
        }
}

// ---------------------------------------------------------------------------
// Kernel 2: row softmax
// ---------------------------------------------------------------------------
__device__ __forceinline__ float warpReduceMax(float m) {
#pragma unroll
    for (int o = 16; o > 0; o >>= 1) m = fmaxf(m, __shfl_xor_sync(0xffffffffu, m, o));
    return m;
}
__device__ __forceinline__ float warpReduceSum(float s) {
#pragma unroll
    for (int o = 16; o > 0; o >>= 1) s += __shfl_xor_sync(0xffffffffu, s, o);
    return s;
}

__global__ __launch_bounds__(256) void softmax_kernel(float* __restrict__ w) {
    float* wr = w + (size_t)blockIdx.x * T_DIM;
    const int tid = threadIdx.x;
    const int lane = tid & 31;
    const int warp = tid >> 5;
    __shared__ float red[8];

    float v[8];
    float4 v0 = *reinterpret_cast<const float4*>(&wr[tid * 4]);
    float4 v1 = *reinterpret_cast<const float4*>(&wr[1024 + tid * 4]);
    v[0] = v0.x; v[1] = v0.y; v[2] = v0.z; v[3] = v0.w;
    v[4] = v1.x; v[5] = v1.y; v[6] = v1.z; v[7] = v1.w;

    float m = v[0];
#pragma unroll
    for (int i = 1; i < 8; i++) m = fmaxf(m, v[i]);
    m = warpReduceMax(m);
    if (lane == 0) red[warp] = m;
    __syncthreads();
    m = red[0];
#pragma unroll
    for (int i = 1; i < 8; i++) m = fmaxf(m, red[i]);
    __syncthreads();

    float s = 0.0f;
#pragma unroll
    for (int i = 0; i < 8; i++) {
        v[i] = expf(v[i] - m);
        s += v[i];
    }
    s = warpReduceSum(s);
    if (lane == 0) red[warp] = s;
    __syncthreads();
    s = red[0];
#pragma unroll
    for (int i = 1; i < 8; i++) s += red[i];

    const float inv = 1.0f / s;
    *reinterpret_cast<float4*>(&wr[tid * 4]) =
        make_float4(v[0] * inv, v[1] * inv, v[2] * inv, v[3] * inv);
    *reinterpret_cast<float4*>(&wr[1024 + tid * 4]) =
        make_float4(v[4] * inv, v[5] * inv, v[6] * inv, v[7] * inv);
}

// ---------------------------------------------------------------------------
// Kernel 3: att_vec = W @ X via fp16-split 3-pass mma. W split in-kernel,
// X from precomputed xT hi/lo (k = s contiguous). Causal K-loop cut.
// ---------------------------------------------------------------------------
__global__ __launch_bounds__(256, 2) void attvec_kernel(const float* __restrict__ w,
                                                        float* __restrict__ out) {
    const int b = blockIdx.z;
    const int rowTile = blockIdx.y;
    const int colTile = blockIdx.x;
    const int rowStart = rowTile * BM;
    const int colStart = colTile * BN;
    const float* wb = w + (size_t)b * T_DIM * T_DIM;
    const __half* xth = g_xTh + (size_t)b * D_DIM * T_DIM;
    const __half* xtl = g_xTl + (size_t)b * D_DIM * T_DIM;
    float* ob = out + (size_t)b * T_DIM * D_DIM;

    __shared__ __half Ah[BM][SSTH], Al[BM][SSTH], Bh[BN][SSTH], Bl[BN][SSTH];

    const int tid = threadIdx.x;
    const int lane = tid & 31, warp = tid >> 5;
    const int wm = (warp & 1) * 64;
    const int wn = (warp >> 1) * 32;
    const int gid = lane >> 2, qid = lane & 3;
    const int lr = tid >> 1;
    const int lk = (tid & 1) * 8;

    float acc[4][4][4];
#pragma unroll
    for (int i = 0; i < 4; i++)
#pragma unroll
        for (int j = 0; j < 4; j++)
#pragma unroll
            for (int q = 0; q < 4; q++) acc[i][j][q] = 0.0f;

    const int numStages = (rowTile == 0) ? (T_DIM / BK) : ((rowTile + 1) * BM / BK);

    for (int st = 0; st < numStages; st++) {
        const int k0 = st * BK;
        float4 av0 = *reinterpret_cast<const float4*>(&wb[(size_t)(rowStart + lr) * T_DIM + k0 + lk]);
        float4 av1 = *reinterpret_cast<const float4*>(&wb[(size_t)(rowStart + lr) * T_DIM + k0 + lk + 4]);
        uint4 bvh = *reinterpret_cast<const uint4*>(&xth[(size_t)(colStart + lr) * T_DIM + k0 + lk]);
        uint4 bvl = *reinterpret_cast<const uint4*>(&xtl[(size_t)(colStart + lr) * T_DIM + k0 + lk]);
        __half hi8[8], lo8[8];
        split_f16(av0.x, hi8[0], lo8[0]); split_f16(av0.y, hi8[1], lo8[1]);
        split_f16(av0.z, hi8[2], lo8[2]); split_f16(av0.w, hi8[3], lo8[3]);
        split_f16(av1.x, hi8[4], lo8[4]); split_f16(av1.y, hi8[5], lo8[5]);
        split_f16(av1.z, hi8[6], lo8[6]); split_f16(av1.w, hi8[7], lo8[7]);
        __syncthreads();
        *reinterpret_cast<uint4*>(&Ah[lr][lk]) = *reinterpret_cast<uint4*>(hi8);
        *reinterpret_cast<uint4*>(&Al[lr][lk]) = *reinterpret_cast<uint4*>(lo8);
        *reinterpret_cast<uint4*>(&Bh[lr][lk]) = bvh;
        *reinterpret_cast<uint4*>(&Bl[lr][lk]) = bvl;
        __syncthreads();

        uint32_t bhf[4][2], blf[4][2];
#pragma unroll
        for (int nt = 0; nt < 4; nt++) {
            const int col = wn + nt * 8 + gid;
            bhf[nt][0] = *reinterpret_cast<const uint32_t*>(&Bh[col][qid * 2]);
            bhf[nt][1] = *reinterpret_cast<const uint32_t*>(&Bh[col][qid * 2 + 8]);
            blf[nt][0] = *reinterpret_cast<const uint32_t*>(&Bl[col][qid * 2]);
            blf[nt][1] = *reinterpret_cast<const uint32_t*>(&Bl[col][qid * 2 + 8]);
        }
#pragma unroll
        for (int mt = 0; mt < 4; mt++) {
            const int row = wm + mt * 16 + gid;
            uint32_t ah[4], al[4];
            ah[0] = *reinterpret_cast<const uint32_t*>(&Ah[row][qid * 2]);
            ah[1] = *reinterpret_cast<const uint32_t*>(&Ah[row + 8][qid * 2]);
            ah[2] = *reinterpret_cast<const uint32_t*>(&Ah[row][qid * 2 + 8]);
            ah[3] = *reinterpret_cast<const uint32_t*>(&Ah[row + 8][qid * 2 + 8]);
            al[0] = *reinterpret_cast<const uint32_t*>(&Al[row][qid * 2]);
            al[1] = *reinterpret_cast<const uint32_t*>(&Al[row + 8][qid * 2]);
            al[2] = *reinterpret_cast<const uint32_t*>(&Al[row][qid * 2 + 8]);
            al[3] = *reinterpret_cast<const uint32_t*>(&Al[row + 8][qid * 2 + 8]);
#pragma unroll
            for (int nt = 0; nt < 4; nt++) {
                mma_f16(acc[mt][nt], ah, bhf[nt]);
                mma_f16(acc[mt][nt], ah, blf[nt]);
                mma_f16(acc[mt][nt], al, bhf[nt]);
            }
        }
    }

#pragma unroll
    for (int mt = 0; mt < 4; mt++)
#pragma unroll
        for (int nt = 0; nt < 4; nt++) {
            float* c = acc[mt][nt];
            const int t0 = rowStart + wm + mt * 16 + gid;
            const int d0 = colStart + wn + nt * 8 + qid * 2;
            *reinterpret_cast<float2*>(&ob[(size_t)t0 * D_DIM + d0]) =
                make_float2(c[0], c[1]);
            *reinterpret_cast<float2*>(&ob[(size_t)(t0 + 8) * D_DIM + d0]) =
                make_float2(c[2], c[3]);
        }
}

// ---------------------------------------------------------------------------
// Launch: d_out = [att_vec (B*T*D) | att_weights (B*T*T)]
// ---------------------------------------------------------------------------
extern "C" void kernel_launch(void* const* d_in, const int* in_sizes, int n_in,
                              void* d_out, int out_size) {
    (void)in_sizes; (void)n_in; (void)out_size;
    const float* x = (const float*)d_in[0];
    float* out = (float*)d_out;
    float* w = out + (size_t)B_DIM * T_DIM * D_DIM;

    dim3 gp(T_DIM / 32, D_DIM / 32, B_DIM);
    prep_kernel<<<gp, dim3(32, 8)>>>(x);

    dim3 g1(T_DIM / BN, T_DIM / BM, B_DIM);
    scores_kernel<<<g1, 256>>>(w);

    softmax_kernel<<<B_DIM * T_DIM, 256>>>(w);

    dim3 g3(D_DIM / BN, T_DIM / BM, B_DIM);
    attvec_kernel<<<g3, 256>>>(w, out);
}

// round 5
// speedup vs baseline: 3.5931x; 1.0355x over previous
#include <cuda_runtime.h>
#include <cuda_fp16.h>
#include <cstdint>

#define B_DIM 8
#define T_DIM 2048
#define D_DIM 1024
#define NEG_INF -1.0e9f

#define BM 128
#define BN 128
#define BK 16
#define SSTH 40                        // smem row stride (halves); conflict-free
#define ARR_HALVES (BM * SSTH)         // 5120 halves per operand array
#define STAGE_HALVES (4 * ARR_HALVES)  // 20480 halves per stage
#define SMEM_BYTES (2 * STAGE_HALVES * 2)  // 81920 B: 2 stages

// fp16 hi/lo split of x, row-major [b][t][d] and transposed [b][d][t]
__device__ __half g_xh [(size_t)B_DIM * T_DIM * D_DIM];
__device__ __half g_xl [(size_t)B_DIM * T_DIM * D_DIM];
__device__ __half g_xTh[(size_t)B_DIM * D_DIM * T_DIM];
__device__ __half g_xTl[(size_t)B_DIM * D_DIM * T_DIM];

__device__ __forceinline__ void mma_f16(float* c, const uint32_t* a, const uint32_t* b) {
    asm volatile(
        "mma.sync.aligned.m16n8k16.row.col.f32.f16.f16.f32 "
        "{%0,%1,%2,%3}, {%4,%5,%6,%7}, {%8,%9}, {%0,%1,%2,%3};\n"
        : "+f"(c[0]), "+f"(c[1]), "+f"(c[2]), "+f"(c[3])
        : "r"(a[0]), "r"(a[1]), "r"(a[2]), "r"(a[3]), "r"(b[0]), "r"(b[1]));
}

__device__ __forceinline__ void split_f16(float v, __half& h, __half& l) {
    h = __float2half_rn(v);
    l = __float2half_rn(v - __half2float(h));
}

// 3-pass (hh + hl + lh) compute of one BK=16 stage from a smem stage buffer.
__device__ __forceinline__ void tile_mma(const __half* S, int wm, int wn,
                                         int gid, int qid,
                                         float (&acc)[4][4][4]) {
    const __half* Ah = S;
    const __half* Al = S + ARR_HALVES;
    const __half* Bh = S + 2 * ARR_HALVES;
    const __half* Bl = S + 3 * ARR_HALVES;
    uint32_t bhf[4][2], blf[4][2];
#pragma unroll
    for (int nt = 0; nt < 4; nt++) {
        const int col = wn + nt * 8 + gid;
        bhf[nt][0] = *reinterpret_cast<const uint32_t*>(&Bh[col * SSTH + qid * 2]);
        bhf[nt][1] = *reinterpret_cast<const uint32_t*>(&Bh[col * SSTH + qid * 2 + 8]);
        blf[nt][0] = *reinterpret_cast<const uint32_t*>(&Bl[col * SSTH + qid * 2]);
        blf[nt][1] = *reinterpret_cast<const uint32_t*>(&Bl[col * SSTH + qid * 2 + 8]);
    }
#pragma unroll
    for (int mt = 0; mt < 4; mt++) {
        const int row = wm + mt * 16 + gid;
        uint32_t ah[4], al[4];
        ah[0] = *reinterpret_cast<const uint32_t*>(&Ah[row * SSTH + qid * 2]);
        ah[1] = *reinterpret_cast<const uint32_t*>(&Ah[(row + 8) * SSTH + qid * 2]);
        ah[2] = *reinterpret_cast<const uint32_t*>(&Ah[row * SSTH + qid * 2 + 8]);
        ah[3] = *reinterpret_cast<const uint32_t*>(&Ah[(row + 8) * SSTH + qid * 2 + 8]);
        al[0] = *reinterpret_cast<const uint32_t*>(&Al[row * SSTH + qid * 2]);
        al[1] = *reinterpret_cast<const uint32_t*>(&Al[(row + 8) * SSTH + qid * 2]);
        al[2] = *reinterpret_cast<const uint32_t*>(&Al[row * SSTH + qid * 2 + 8]);
        al[3] = *reinterpret_cast<const uint32_t*>(&Al[(row + 8) * SSTH + qid * 2 + 8]);
#pragma unroll
        for (int nt = 0; nt < 4; nt++) {
            mma_f16(acc[mt][nt], ah, bhf[nt]);
            mma_f16(acc[mt][nt], ah, blf[nt]);
            mma_f16(acc[mt][nt], al, bhf[nt]);
        }
    }
}

// ---------------------------------------------------------------------------
// Prep: fp16 split of x into [t][d] and [d][t] layouts.
// ---------------------------------------------------------------------------
__global__ __launch_bounds__(256) void prep_kernel(const float* __restrict__ x) {
    __shared__ float tile[32][33];
    const int b = blockIdx.z;
    const int t0 = blockIdx.x * 32;
    const int d0 = blockIdx.y * 32;
    const float* xb = x + (size_t)b * T_DIM * D_DIM;
    const int tx = threadIdx.x;
    const int ty = threadIdx.y;
    const size_t base = (size_t)b * T_DIM * D_DIM;
#pragma unroll
    for (int i = 0; i < 32; i += 8) {
        float v = xb[(size_t)(t0 + ty + i) * D_DIM + d0 + tx];
        tile[ty + i][tx] = v;
        __half h, l;
        split_f16(v, h, l);
        g_xh[base + (size_t)(t0 + ty + i) * D_DIM + d0 + tx] = h;
        g_xl[base + (size_t)(t0 + ty + i) * D_DIM + d0 + tx] = l;
    }
    __syncthreads();
#pragma unroll
    for (int i = 0; i < 32; i += 8) {
        float v = tile[tx][ty + i];
        __half h, l;
        split_f16(v, h, l);
        g_xTh[base + (size_t)(d0 + ty + i) * T_DIM + t0 + tx] = h;
        g_xTl[base + (size_t)(d0 + ty + i) * T_DIM + t0 + tx] = l;
    }
}

// ---------------------------------------------------------------------------
// Kernel 1: raw scores = x @ x^T, lower-triangle tiles only (softmax masks).
// 2-stage double-buffered pipeline, one __syncthreads per stage.
// ---------------------------------------------------------------------------
__global__ __launch_bounds__(256, 2) void scores_kernel(float* __restrict__ w) {
    extern __shared__ __half sm[];
    const int b = blockIdx.y;
    const int i = blockIdx.x;
    int r = (int)((sqrtf(8.0f * i + 1.0f) - 1.0f) * 0.5f);
    while ((r + 1) * (r + 2) / 2 <= i) ++r;
    while (r * (r + 1) / 2 > i) --r;
    const int c = i - r * (r + 1) / 2;
    const int rowStart = r * BM;
    const int colStart = c * BN;
    float* wb = w + (size_t)b * T_DIM * T_DIM;
    const __half* xhb = g_xh + (size_t)b * T_DIM * D_DIM;
    const __half* xlb = g_xl + (size_t)b * T_DIM * D_DIM;

    const int tid = threadIdx.x;
    const int lane = tid & 31, warp = tid >> 5;
    const int wm = (warp & 1) * 64;
    const int wn = (warp >> 1) * 32;
    const int gid = lane >> 2, qid = lane & 3;
    const int lr = tid >> 1;
    const int lk = (tid & 1) * 8;

    float acc[4][4][4];
#pragma unroll
    for (int a = 0; a < 4; a++)
#pragma unroll
        for (int bb = 0; bb < 4; bb++)
#pragma unroll
            for (int q = 0; q < 4; q++) acc[a][bb][q] = 0.0f;

    const size_t aoff = (size_t)(rowStart + lr) * D_DIM + lk;
    const size_t boff = (size_t)(colStart + lr) * D_DIM + lk;

    uint4 avh = *reinterpret_cast<const uint4*>(&xhb[aoff]);
    uint4 avl = *reinterpret_cast<const uint4*>(&xlb[aoff]);
    uint4 bvh = *reinterpret_cast<const uint4*>(&xhb[boff]);
    uint4 bvl = *reinterpret_cast<const uint4*>(&xlb[boff]);
    {
        __half* S = sm;
        *reinterpret_cast<uint4*>(&S[lr * SSTH + lk]) = avh;
        *reinterpret_cast<uint4*>(&S[ARR_HALVES + lr * SSTH + lk]) = avl;
        *reinterpret_cast<uint4*>(&S[2 * ARR_HALVES + lr * SSTH + lk]) = bvh;
        *reinterpret_cast<uint4*>(&S[3 * ARR_HALVES + lr * SSTH + lk]) = bvl;
    }
    __syncthreads();

    const int numStages = D_DIM / BK;  // 64
    for (int st = 0; st < numStages; st++) {
        if (st + 1 < numStages) {
            const size_t a2 = aoff + (size_t)(st + 1) * BK;
            const size_t b2 = boff + (size_t)(st + 1) * BK;
            avh = *reinterpret_cast<const uint4*>(&xhb[a2]);
            avl = *reinterpret_cast<const uint4*>(&xlb[a2]);
            bvh = *reinterpret_cast<const uint4*>(&xhb[b2]);
            bvl = *reinterpret_cast<const uint4*>(&xlb[b2]);
        }
        tile_mma(sm + (st & 1) * STAGE_HALVES, wm, wn, gid, qid, acc);
        if (st + 1 < numStages) {
            __half* D = sm + ((st + 1) & 1) * STAGE_HALVES;
            *reinterpret_cast<uint4*>(&D[lr * SSTH + lk]) = avh;
            *reinterpret_cast<uint4*>(&D[ARR_HALVES + lr * SSTH + lk]) = avl;
            *reinterpret_cast<uint4*>(&D[2 * ARR_HALVES + lr * SSTH + lk]) = bvh;
            *reinterpret_cast<uint4*>(&D[3 * ARR_HALVES + lr * SSTH + lk]) = bvl;
        }
        __syncthreads();
    }

#pragma unroll
    for (int mt = 0; mt < 4; mt++)
#pragma unroll
        for (int nt = 0; nt < 4; nt++) {
            float* cc = acc[mt][nt];
            const int t0 = rowStart + wm + mt * 16 + gid;
            const int s0 = colStart + wn + nt * 8 + qid * 2;
            *reinterpret_cast<float2*>(&wb[(size_t)t0 * T_DIM + s0]) =
                make_float2(cc[0], cc[1]);
            *reinterpret_cast<float2*>(&wb[(size_t)(t0 + 8) * T_DIM + s0]) =
                make_float2(cc[2], cc[3]);
        }
}

// ---------------------------------------------------------------------------
// Kernel 2: masked row softmax. Masks s >= t with -1e9 (row 0 -> uniform),
// skips loading fully-masked float4s, writes the full row (zeros above diag).
// ---------------------------------------------------------------------------
__device__ __forceinline__ float warpReduceMax(float m) {
#pragma unroll
    for (int o = 16; o > 0; o >>= 1) m = fmaxf(m, __shfl_xor_sync(0xffffffffu, m, o));
    return m;
}
__device__ __forceinline__ float warpReduceSum(float s) {
#pragma unroll
    for (int o = 16; o > 0; o >>= 1) s += __shfl_xor_sync(0xffffffffu, s, o);
    return s;
}

__global__ __launch_bounds__(256) void softmax_kernel(float* __restrict__ w) {
    const int row = blockIdx.x;
    const int t = row & (T_DIM - 1);
    float* wr = w + (size_t)row * T_DIM;
    const int tid = threadIdx.x;
    const int lane = tid & 31;
    const int warp = tid >> 5;
    __shared__ float red[8];

    const int s0 = tid * 4;
    const int s1 = 1024 + tid * 4;
    float v[8];
    if (s0 < t) {
        float4 x = *reinterpret_cast<const float4*>(&wr[s0]);
        v[0] = x.x; v[1] = x.y; v[2] = x.z; v[3] = x.w;
    } else {
        v[0] = v[1] = v[2] = v[3] = NEG_INF;
    }
    if (s1 < t) {
        float4 x = *reinterpret_cast<const float4*>(&wr[s1]);
        v[4] = x.x; v[5] = x.y; v[6] = x.z; v[7] = x.w;
    } else {
        v[4] = v[5] = v[6] = v[7] = NEG_INF;
    }
#pragma unroll
    for (int k = 0; k < 4; k++) v[k] = (s0 + k < t) ? v[k] : NEG_INF;
#pragma unroll
    for (int k = 0; k < 4; k++) v[4 + k] = (s1 + k < t) ? v[4 + k] : NEG_INF;

    float m = v[0];
#pragma unroll
    for (int k = 1; k < 8; k++) m = fmaxf(m, v[k]);
    m = warpReduceMax(m);
    if (lane == 0) red[warp] = m;
    __syncthreads();
    m = red[0];
#pragma unroll
    for (int k = 1; k < 8; k++) m = fmaxf(m, red[k]);
    __syncthreads();

    float s = 0.0f;
#pragma unroll
    for (int k = 0; k < 8; k++) {
        v[k] = expf(v[k] - m);
        s += v[k];
    }
    s = warpReduceSum(s);
    if (lane == 0) red[warp] = s;
    __syncthreads();
    s = red[0];
#pragma unroll
    for (int k = 1; k < 8; k++) s += red[k];

    const float inv = 1.0f / s;
    *reinterpret_cast<float4*>(&wr[s0]) =
        make_float4(v[0] * inv, v[1] * inv, v[2] * inv, v[3] * inv);
    *reinterpret_cast<float4*>(&wr[s1]) =
        make_float4(v[4] * inv, v[5] * inv, v[6] * inv, v[7] * inv);
}

// ---------------------------------------------------------------------------
// Kernel 3: att_vec = W @ X, double-buffered, W split in-kernel, causal K cut.
// ---------------------------------------------------------------------------
__global__ __launch_bounds__(256, 2) void attvec_kernel(const float* __restrict__ w,
                                                        float* __restrict__ out) {
    extern __shared__ __half sm[];
    const int b = blockIdx.z;
    const int rowTile = blockIdx.y;
    const int colTile = blockIdx.x;
    const int rowStart = rowTile * BM;
    const int colStart = colTile * BN;
    const float* wb = w + (size_t)b * T_DIM * T_DIM;
    const __half* xth = g_xTh + (size_t)b * D_DIM * T_DIM;
    const __half* xtl = g_xTl + (size_t)b * D_DIM * T_DIM;
    float* ob = out + (size_t)b * T_DIM * D_DIM;

    const int tid = threadIdx.x;
    const int lane = tid & 31, warp = tid >> 5;
    const int wm = (warp & 1) * 64;
    const int wn = (warp >> 1) * 32;
    const int gid = lane >> 2, qid = lane & 3;
    const int lr = tid >> 1;
    const int lk = (tid & 1) * 8;

    float acc[4][4][4];
#pragma unroll
    for (int a = 0; a < 4; a++)
#pragma unroll
        for (int bb = 0; bb < 4; bb++)
#pragma unroll
            for (int q = 0; q < 4; q++) acc[a][bb][q] = 0.0f;

    const int numStages = (rowTile == 0) ? (T_DIM / BK) : ((rowTile + 1) * BM / BK);
    const size_t aoff = (size_t)(rowStart + lr) * T_DIM + lk;
    const size_t boff = (size_t)(colStart + lr) * T_DIM + lk;

    float4 av0 = *reinterpret_cast<const float4*>(&wb[aoff]);
    float4 av1 = *reinterpret_cast<const float4*>(&wb[aoff + 4]);
    uint4 bvh = *reinterpret_cast<const uint4*>(&xth[boff]);
    uint4 bvl = *reinterpret_cast<const uint4*>(&xtl[boff]);
    {
        __half hi8[8], lo8[8];
        split_f16(av0.x, hi8[0], lo8[0]); split_f16(av0.y, hi8[1], lo8[1]);
        split_f16(av0.z, hi8[2], lo8[2]); split_f16(av0.w, hi8[3], lo8[3]);
        split_f16(av1.x, hi8[4], lo8[4]); split_f16(av1.y, hi8[5], lo8[5]);
        split_f16(av1.z, hi8[6], lo8[6]); split_f16(av1.w, hi8[7], lo8[7]);
        __half* S = sm;
        *reinterpret_cast<uint4*>(&S[lr * SSTH + lk]) = *reinterpret_cast<uint4*>(hi8);
        *reinterpret_cast<uint4*>(&S[ARR_HALVES + lr * SSTH + lk]) = *reinterpret_cast<uint4*>(lo8);
        *reinterpret_cast<uint4*>(&S[2 * ARR_HALVES + lr * SSTH + lk]) = bvh;
        *reinterpret_cast<uint4*>(&S[3 * ARR_HALVES + lr * SSTH + lk]) = bvl;
    }
    __syncthreads();

    for (int st = 0; st < numStages; st++) {
        if (st + 1 < numStages) {
            const size_t a2 = aoff + (size_t)(st + 1) * BK;
            const size_t b2 = boff + (size_t)(st + 1) * BK;
            av0 = *reinterpret_cast<const float4*>(&wb[a2]);
            av1 = *reinterpret_cast<const float4*>(&wb[a2 + 4]);
            bvh = *reinterpret_cast<const uint4*>(&xth[b2]);
            bvl = *reinterpret_cast<const uint4*>(&xtl[b2]);
        }
        tile_mma(sm + (st & 1) * STAGE_HALVES, wm, wn, gid, qid, acc);
        if (st + 1 < numStages) {
            __half hi8[8], lo8[8];
            split_f16(av0.x, hi8[0], lo8[0]); split_f16(av0.y, hi8[1], lo8[1]);
            split_f16(av0.z, hi8[2], lo8[2]); split_f16(av0.w, hi8[3], lo8[3]);
            split_f16(av1.x, hi8[4], lo8[4]); split_f16(av1.y, hi8[5], lo8[5]);
            split_f16(av1.z, hi8[6], lo8[6]); split_f16(av1.w, hi8[7], lo8[7]);
            __half* D = sm + ((st + 1) & 1) * STAGE_HALVES;
            *reinterpret_cast<uint4*>(&D[lr * SSTH + lk]) = *reinterpret_cast<uint4*>(hi8);
            *reinterpret_cast<uint4*>(&D[ARR_HALVES + lr * SSTH + lk]) = *reinterpret_cast<uint4*>(lo8);
            *reinterpret_cast<uint4*>(&D[2 * ARR_HALVES + lr * SSTH + lk]) = bvh;
            *reinterpret_cast<uint4*>(&D[3 * ARR_HALVES + lr * SSTH + lk]) = bvl;
        }
        __syncthreads();
    }

#pragma unroll
    for (int mt = 0; mt < 4; mt++)
#pragma unroll
        for (int nt = 0; nt < 4; nt++) {
            float* cc = acc[mt][nt];
            const int t0 = rowStart + wm + mt * 16 + gid;
            const int d0 = colStart + wn + nt * 8 + qid * 2;
            *reinterpret_cast<float2*>(&ob[(size_t)t0 * D_DIM + d0]) =
                make_float2(cc[0], cc[1]);
            *reinterpret_cast<float2*>(&ob[(size_t)(t0 + 8) * D_DIM + d0]) =
                make_float2(cc[2], cc[3]);
        }
}

// ---------------------------------------------------------------------------
// Launch: d_out = [att_vec (B*T*D) | att_weights (B*T*T)]
// ---------------------------------------------------------------------------
extern "C" void kernel_launch(void* const* d_in, const int* in_sizes, int n_in,
                              void* d_out, int out_size) {
    (void)in_sizes; (void)n_in; (void)out_size;
    const float* x = (const float*)d_in[0];
    float* out = (float*)d_out;
    float* w = out + (size_t)B_DIM * T_DIM * D_DIM;

    cudaFuncSetAttribute(scores_kernel, cudaFuncAttributeMaxDynamicSharedMemorySize, SMEM_BYTES);
    cudaFuncSetAttribute(attvec_kernel, cudaFuncAttributeMaxDynamicSharedMemorySize, SMEM_BYTES);

    dim3 gp(T_DIM / 32, D_DIM / 32, B_DIM);
    prep_kernel<<<gp, dim3(32, 8)>>>(x);

    const int nTri = (T_DIM / BM) * (T_DIM / BM + 1) / 2;  // 136
    scores_kernel<<<dim3(nTri, B_DIM), 256, SMEM_BYTES>>>(w);

    softmax_kernel<<<B_DIM * T_DIM, 256>>>(w);

    dim3 g3(D_DIM / BN, T_DIM / BM, B_DIM);
    attvec_kernel<<<g3, 256, SMEM_BYTES>>>(w, out);
}